// round 1
// baseline (speedup 1.0000x reference)
#include <cuda_runtime.h>
#include <math.h>

// ---------------- problem constants ----------------
#define BB     4
#define TTOK   512
#define LIMG   256
#define TT     768          // LIMG + TTOK
#define CC     768
#define HH     12
#define DH     64
#define NLAYER 12
#define VV     50257
#define RR     4
#define LSCALE 8.0f         // ALPHA / R = 32/4
#define C3     2304
#define C4     3072
#define BT     (BB*TT)      // 3072
#define ATT_ELEMS   (BB*HH*TT*TT)      // 28311552
#define LOGITS_ELEMS ((long long)BB*TTOK*VV) // 102926336

// ---------------- scratch (device globals; no allocs allowed) ----------------
__device__ float g_x  [BB*TT*CC];
__device__ float g_h  [BB*TT*CC];
__device__ float g_qkv[BB*TT*C3];
__device__ float g_att[ATT_ELEMS];
__device__ float g_y  [BB*TT*CC];
__device__ float g_m  [BB*TT*C4];
__device__ float g_lo [BT*RR];
__device__ float g_xt [BB*TTOK*CC];
__device__ int   g_tok_is64;

// ---------------- packed f32x2 helpers (FFMA2: ptxas never emits; PTX-only) ----
__device__ __forceinline__ unsigned long long pk2(float x, float y) {
    unsigned long long r;
    asm("mov.b64 %0, {%1,%2};" : "=l"(r) : "f"(x), "f"(y));
    return r;
}
__device__ __forceinline__ void upk2(unsigned long long p, float& x, float& y) {
    asm("mov.b64 {%0,%1}, %2;" : "=f"(x), "=f"(y) : "l"(p));
}
__device__ __forceinline__ void fma2(unsigned long long& d, unsigned long long a, unsigned long long b) {
    asm("fma.rn.f32x2 %0, %1, %2, %0;" : "+l"(d) : "l"(a), "l"(b));
}

// ---------------- block reductions (256 threads) ----------------
__device__ __forceinline__ float bsum(float v) {
    __shared__ float sh[32];
    #pragma unroll
    for (int o = 16; o; o >>= 1) v += __shfl_xor_sync(0xffffffffu, v, o);
    if ((threadIdx.x & 31) == 0) sh[threadIdx.x >> 5] = v;
    __syncthreads();
    if (threadIdx.x == 0) {
        float s = 0.f;
        int nw = blockDim.x >> 5;
        for (int i = 0; i < nw; i++) s += sh[i];
        sh[0] = s;
    }
    __syncthreads();
    float r = sh[0];
    __syncthreads();
    return r;
}
__device__ __forceinline__ float bmax(float v) {
    __shared__ float sh[32];
    #pragma unroll
    for (int o = 16; o; o >>= 1) v = fmaxf(v, __shfl_xor_sync(0xffffffffu, v, o));
    if ((threadIdx.x & 31) == 0) sh[threadIdx.x >> 5] = v;
    __syncthreads();
    if (threadIdx.x == 0) {
        float s = -3.0e38f;
        int nw = blockDim.x >> 5;
        for (int i = 0; i < nw; i++) s = fmaxf(s, sh[i]);
        sh[0] = s;
    }
    __syncthreads();
    float r = sh[0];
    __syncthreads();
    return r;
}

// ---------------- token dtype probe ----------------
// If tokens were saved as int64 (little-endian), every odd 32-bit word of the
// first 1024 tokens is the zero high-half. If int32, odd words are random
// tokens in [0,50257) -> P(all zero) ~ 0.
__global__ void detect_kernel(const int* __restrict__ tok32) {
    __shared__ int bad;
    if (threadIdx.x == 0) bad = 0;
    __syncthreads();
    for (int i = threadIdx.x; i < 1024; i += blockDim.x)
        if (tok32[2 * i + 1] != 0) bad = 1;
    __syncthreads();
    if (threadIdx.x == 0) g_tok_is64 = (bad == 0) ? 1 : 0;
}

// ---------------- embedding: x = concat(img, wte[tok]+wpe[pos]) ----------------
__global__ void embed_kernel(const int* __restrict__ tok32,
                             const float* __restrict__ img,
                             const float* __restrict__ wte,
                             const float* __restrict__ wpe,
                             float* __restrict__ x) {
    int idx = blockIdx.x * blockDim.x + threadIdx.x;   // over BB*TT*CC
    int b = idx / (TT * CC);
    int r = idx - b * (TT * CC);
    int t = r / CC;
    int c = r - t * CC;
    float v;
    if (t < LIMG) {
        v = img[((long long)b * LIMG + t) * CC + c];
    } else {
        int tt = t - LIMG;
        int tix = b * TTOK + tt;
        int tok = g_tok_is64 ? tok32[2 * tix] : tok32[tix];
        v = wte[(long long)tok * CC + c] + wpe[(long long)tt * CC + c];
    }
    x[idx] = v;
}

// ---------------- layernorm (row length CC, eps 1e-5) ----------------
__global__ void ln_kernel(const float* __restrict__ in,
                          const float* __restrict__ g,
                          const float* __restrict__ b,
                          float* __restrict__ out) {
    long long row = blockIdx.x;
    const float* xr = in + row * CC;
    float* orow = out + row * CC;
    float s = 0.f;
    for (int c = threadIdx.x; c < CC; c += blockDim.x) s += xr[c];
    float mean = bsum(s) * (1.0f / CC);
    float s2 = 0.f;
    for (int c = threadIdx.x; c < CC; c += blockDim.x) {
        float d = xr[c] - mean; s2 += d * d;
    }
    float var = bsum(s2) * (1.0f / CC);
    float inv = rsqrtf(var + 1e-5f);
    for (int c = threadIdx.x; c < CC; c += blockDim.x)
        orow[c] = (xr[c] - mean) * inv * g[c] + b[c];
}

// ---------------- causal softmax over att rows (writes 0 beyond t) ------------
__global__ void softmax_kernel(float* __restrict__ att) {
    long long row = blockIdx.x;          // (b*H + h)*T + q
    int t = (int)(row % TT);
    int len = t + 1;
    float* p = att + row * TT;
    float mx = -3.0e38f;
    for (int j = threadIdx.x; j < len; j += blockDim.x) mx = fmaxf(mx, p[j]);
    mx = bmax(mx);
    float s = 0.f;
    for (int j = threadIdx.x; j < len; j += blockDim.x) {
        float e = __expf(p[j] - mx);
        p[j] = e; s += e;
    }
    s = bsum(s);
    float inv = 1.0f / s;
    for (int j = threadIdx.x; j < TT; j += blockDim.x)
        p[j] = (j < len) ? p[j] * inv : 0.0f;
}

// ---------------- gelu (tanh approx) ----------------
__global__ void gelu_kernel(float* __restrict__ p, int n) {
    int i = blockIdx.x * blockDim.x + threadIdx.x;
    if (i < n) {
        float x = p[i];
        float u = 0.7978845608028654f * (x + 0.044715f * x * x * x);
        p[i] = 0.5f * x * (1.0f + tanhf(u));
    }
}

// ---------------- LoRA down: tmp[M,4] = X[M,K] @ A[K,4] ----------------
__global__ void lora_down_kernel(const float* __restrict__ X, int K,
                                 const float* __restrict__ Ad,
                                 float* __restrict__ outT) {
    int m = blockIdx.x;
    const float* xr = X + (long long)m * K;
    float a0 = 0, a1 = 0, a2 = 0, a3 = 0;
    for (int k = threadIdx.x; k < K; k += blockDim.x) {
        float xv = xr[k];
        float4 av = *reinterpret_cast<const float4*>(Ad + (long long)k * 4);
        a0 += xv * av.x; a1 += xv * av.y; a2 += xv * av.z; a3 += xv * av.w;
    }
    __shared__ float sh[128 * 4];
    int tid = threadIdx.x;
    sh[tid * 4 + 0] = a0; sh[tid * 4 + 1] = a1; sh[tid * 4 + 2] = a2; sh[tid * 4 + 3] = a3;
    __syncthreads();
    for (int s = 64; s > 0; s >>= 1) {
        if (tid < s) {
            sh[tid * 4 + 0] += sh[(tid + s) * 4 + 0];
            sh[tid * 4 + 1] += sh[(tid + s) * 4 + 1];
            sh[tid * 4 + 2] += sh[(tid + s) * 4 + 2];
            sh[tid * 4 + 3] += sh[(tid + s) * 4 + 3];
        }
        __syncthreads();
    }
    if (tid == 0) {
        outT[m * 4 + 0] = sh[0]; outT[m * 4 + 1] = sh[1];
        outT[m * 4 + 2] = sh[2]; outT[m * 4 + 3] = sh[3];
    }
}

// ---------------- LoRA up: out[m, n] += SCALE * tmp[m,:] @ B[:, n] -------------
__global__ void lora_up_kernel(const float* __restrict__ T4,
                               const float* __restrict__ Bu,
                               float* __restrict__ out,
                               long long ldc, int N) {
    int n = blockIdx.x * blockDim.x + threadIdx.x;
    int m = blockIdx.y;
    if (n >= N) return;
    float4 t = *reinterpret_cast<const float4*>(T4 + m * 4);
    float v = t.x * Bu[n] + t.y * Bu[(long long)N + n]
            + t.z * Bu[2LL * N + n] + t.w * Bu[3LL * N + n];
    out[(long long)m * ldc + n] += LSCALE * v;
}

// ---------------- copy final-LN token rows into contiguous xt ------------------
__global__ void copy_xt_kernel(const float* __restrict__ hbuf, float* __restrict__ xt) {
    int idx = blockIdx.x * blockDim.x + threadIdx.x;   // over BB*TTOK*CC
    int m = idx / CC, c = idx - m * CC;
    int b = m / TTOK, t = LIMG + (m - b * TTOK);
    xt[idx] = hbuf[((long long)b * TT + t) * CC + c];
}

// ---------------- copy att_map (layer 11) into d_out tail ----------------
__global__ void copy_att_kernel(float* __restrict__ dst) {
    int i = blockIdx.x * blockDim.x + threadIdx.x;     // over ATT_ELEMS/4
    reinterpret_cast<float4*>(dst)[i] = reinterpret_cast<const float4*>(g_att)[i];
}

// ---------------- generic batched SGEMM (64x64x16, FFMA2 inner loop) ----------
// C[m,n] = alpha * sum_k A[m,k] * B(k,n) (+ bias[n]) (+ old C if acc)
// B(k,n) = TRANSB ? B[n*ldb + k] : B[k*ldb + n]
// Per-z offsets: z -> (zb = z/Hdiv, zh = z%Hdiv); off = zb*s?b + zh*s?h.
template<bool TRANSB>
__global__ void __launch_bounds__(256) gemm_kernel(
    const float* __restrict__ A, const float* __restrict__ B, float* __restrict__ C,
    const float* __restrict__ bias,
    int M, int N, int K, int lda, int ldb, int ldc,
    long long sAb, long long sAh, long long sBb, long long sBh,
    long long sCb, long long sCh, int Hdiv, float alpha, int acc)
{
    __shared__ __align__(16) float As[16][64];
    __shared__ __align__(16) float Bs[16][64];
    {
        int z = blockIdx.z;
        int zb = z / Hdiv, zh = z - zb * Hdiv;
        A += zb * sAb + (long long)zh * sAh;
        B += zb * sBb + (long long)zh * sBh;
        C += zb * sCb + (long long)zh * sCh;
    }
    const int m0 = blockIdx.y * 64, n0 = blockIdx.x * 64;
    const int tid = threadIdx.x;
    const int tx = tid & 15, ty = tid >> 4;
    unsigned long long accp[4][2];
    #pragma unroll
    for (int i = 0; i < 4; i++) { accp[i][0] = 0ull; accp[i][1] = 0ull; }
    const int alr = tid >> 2, alc = (tid & 3) << 2;

    for (int kt = 0; kt < K; kt += 16) {
        // A tile -> As[k][m]
        float4 av = make_float4(0.f, 0.f, 0.f, 0.f);
        if (m0 + alr < M)
            av = *reinterpret_cast<const float4*>(A + (long long)(m0 + alr) * lda + (kt + alc));
        As[alc + 0][alr] = av.x; As[alc + 1][alr] = av.y;
        As[alc + 2][alr] = av.z; As[alc + 3][alr] = av.w;
        // B tile -> Bs[k][n]
        if (!TRANSB) {
            int br = tid >> 4, bc = (tid & 15) << 2;
            float4 bv = make_float4(0.f, 0.f, 0.f, 0.f);
            int gn = n0 + bc;
            const float* bp = B + (long long)(kt + br) * ldb + gn;
            if (gn + 3 < N) bv = *reinterpret_cast<const float4*>(bp);
            else {
                if (gn < N)     bv.x = bp[0];
                if (gn + 1 < N) bv.y = bp[1];
                if (gn + 2 < N) bv.z = bp[2];
            }
            *reinterpret_cast<float4*>(&Bs[br][bc]) = bv;
        } else {
            int bn = tid >> 2, bk = (tid & 3) << 2;
            float4 bv = make_float4(0.f, 0.f, 0.f, 0.f);
            if (n0 + bn < N)
                bv = *reinterpret_cast<const float4*>(B + (long long)(n0 + bn) * ldb + (kt + bk));
            Bs[bk + 0][bn] = bv.x; Bs[bk + 1][bn] = bv.y;
            Bs[bk + 2][bn] = bv.z; Bs[bk + 3][bn] = bv.w;
        }
        __syncthreads();
        #pragma unroll
        for (int k = 0; k < 16; k++) {
            float4 a = *reinterpret_cast<const float4*>(&As[k][ty << 2]);
            ulonglong2 bq = *reinterpret_cast<const ulonglong2*>(&Bs[k][tx << 2]);
            float aa[4] = {a.x, a.y, a.z, a.w};
            #pragma unroll
            for (int i = 0; i < 4; i++) {
                unsigned long long ai = pk2(aa[i], aa[i]);
                fma2(accp[i][0], ai, bq.x);
                fma2(accp[i][1], ai, bq.y);
            }
        }
        __syncthreads();
    }
    #pragma unroll
    for (int i = 0; i < 4; i++) {
        float c0, c1, c2, c3;
        upk2(accp[i][0], c0, c1);
        upk2(accp[i][1], c2, c3);
        float cv[4] = {c0, c1, c2, c3};
        int gm = m0 + (ty << 2) + i;
        if (gm >= M) continue;
        #pragma unroll
        for (int j = 0; j < 4; j++) {
            int gn = n0 + (tx << 2) + j;
            if (gn >= N) continue;
            float v = alpha * cv[j];
            if (bias) v += bias[gn];
            long long off = (long long)gm * ldc + gn;
            if (acc) v += C[off];
            C[off] = v;
        }
    }
}

// ---------------- host-side launch helpers ----------------
static void gemm(bool tb, const float* A, const float* B, float* C, const float* bias,
                 int M, int N, int K, int lda, int ldb, int ldc,
                 long long sAb, long long sAh, long long sBb, long long sBh,
                 long long sCb, long long sCh, int Hdiv, int Z, float alpha, int acc) {
    dim3 gr((N + 63) / 64, (M + 63) / 64, Z);
    if (tb) gemm_kernel<true><<<gr, 256>>>(A, B, C, bias, M, N, K, lda, ldb, ldc,
                                           sAb, sAh, sBb, sBh, sCb, sCh, Hdiv, alpha, acc);
    else    gemm_kernel<false><<<gr, 256>>>(A, B, C, bias, M, N, K, lda, ldb, ldc,
                                            sAb, sAh, sBb, sBh, sCb, sCh, Hdiv, alpha, acc);
}

static void lora(const float* X, int M, int K, const float* Ad, const float* Bu,
                 float* out, long long ldc, int colofs, int N, float* lobuf) {
    lora_down_kernel<<<M, 128>>>(X, K, Ad, lobuf);
    dim3 gr((N + 255) / 256, M);
    lora_up_kernel<<<gr, 256>>>(lobuf, Bu, out + colofs, ldc, N);
}

extern "C" void kernel_launch(void* const* d_in, const int* in_sizes, int n_in,
                              void* d_out, int out_size) {
    (void)in_sizes; (void)n_in; (void)out_size;
    const int*   tok  = (const int*)  d_in[0];
    const float* img  = (const float*)d_in[1];
    const float* wte  = (const float*)d_in[2];
    const float* wpe  = (const float*)d_in[3];
    const float* ln1g = (const float*)d_in[4];
    const float* ln1b = (const float*)d_in[5];
    const float* Wqkv = (const float*)d_in[6];
    const float* bqkv = (const float*)d_in[7];
    const float* Aq   = (const float*)d_in[8];
    const float* Bq   = (const float*)d_in[9];
    const float* Av   = (const float*)d_in[10];
    const float* Bv   = (const float*)d_in[11];
    const float* Wo   = (const float*)d_in[12];
    const float* bo   = (const float*)d_in[13];
    const float* Ao   = (const float*)d_in[14];
    const float* Bo   = (const float*)d_in[15];
    const float* ln2g = (const float*)d_in[16];
    const float* ln2b = (const float*)d_in[17];
    const float* Wfc  = (const float*)d_in[18];
    const float* bfc  = (const float*)d_in[19];
    const float* Afc  = (const float*)d_in[20];
    const float* Bfc  = (const float*)d_in[21];
    const float* Wp2  = (const float*)d_in[22];
    const float* bp2  = (const float*)d_in[23];
    const float* Ap2  = (const float*)d_in[24];
    const float* Bp2  = (const float*)d_in[25];
    const float* lnfg = (const float*)d_in[26];
    const float* lnfb = (const float*)d_in[27];
    const float* Alm  = (const float*)d_in[28];
    const float* Blm  = (const float*)d_in[29];
    float* out = (float*)d_out;

    float *x, *h, *qkv, *att, *y, *mb, *lo, *xt;
    cudaGetSymbolAddress((void**)&x,   g_x);
    cudaGetSymbolAddress((void**)&h,   g_h);
    cudaGetSymbolAddress((void**)&qkv, g_qkv);
    cudaGetSymbolAddress((void**)&att, g_att);
    cudaGetSymbolAddress((void**)&y,   g_y);
    cudaGetSymbolAddress((void**)&mb,  g_m);
    cudaGetSymbolAddress((void**)&lo,  g_lo);
    cudaGetSymbolAddress((void**)&xt,  g_xt);

    detect_kernel<<<1, 256>>>(tok);
    embed_kernel<<<(BB * TT * CC) / 256, 256>>>(tok, img, wte, wpe, x);

    const float ascale = 1.0f / 8.0f;   // 1/sqrt(64)
    for (int i = 0; i < NLAYER; i++) {
        // ln1
        ln_kernel<<<BT, 256>>>(x, ln1g + i * CC, ln1b + i * CC, h);
        // qkv = h @ Wqkv + bqkv
        gemm(false, h, Wqkv + (long long)i * CC * C3, qkv, bqkv + i * C3,
             BT, C3, CC, CC, C3, C3, 0, 0, 0, 0, 0, 0, 1, 1, 1.0f, 0);
        // q/v LoRA into qkv columns
        lora(h, BT, CC, Aq + (long long)i * CC * RR, Bq + (long long)i * RR * CC, qkv, C3, 0,    CC, lo);
        lora(h, BT, CC, Av + (long long)i * CC * RR, Bv + (long long)i * RR * CC, qkv, C3, 2*CC, CC, lo);
        // scores: att[b,h,q,k] = (1/8) q . k
        gemm(true, qkv, qkv + CC, att, nullptr,
             TT, TT, DH, C3, C3, TT,
             (long long)TT * C3, DH, (long long)TT * C3, DH,
             (long long)HH * TT * TT, (long long)TT * TT, HH, BB * HH, ascale, 0);
        softmax_kernel<<<BB * HH * TT, 256>>>(att);
        // y = att @ v  (written directly in (B,T,C) head-concat layout)
        gemm(false, att, qkv + 2 * CC, y, nullptr,
             TT, DH, TT, TT, C3, CC,
             (long long)HH * TT * TT, (long long)TT * TT,
             (long long)TT * C3, DH,
             (long long)TT * CC, DH, HH, BB * HH, 1.0f, 0);
        // x += y @ Wo + bo ; x += LoRA_o(y)
        gemm(false, y, Wo + (long long)i * CC * CC, x, bo + i * CC,
             BT, CC, CC, CC, CC, CC, 0, 0, 0, 0, 0, 0, 1, 1, 1.0f, 1);
        lora(y, BT, CC, Ao + (long long)i * CC * RR, Bo + (long long)i * RR * CC, x, CC, 0, CC, lo);
        // ln2
        ln_kernel<<<BT, 256>>>(x, ln2g + i * CC, ln2b + i * CC, h);
        // m = h @ Wfc + bfc + LoRA_fc(h); gelu
        gemm(false, h, Wfc + (long long)i * CC * C4, mb, bfc + i * C4,
             BT, C4, CC, CC, C4, C4, 0, 0, 0, 0, 0, 0, 1, 1, 1.0f, 0);
        lora(h, BT, CC, Afc + (long long)i * CC * RR, Bfc + (long long)i * RR * C4, mb, C4, 0, C4, lo);
        gelu_kernel<<<(BT * C4) / 256, 256>>>(mb, BT * C4);
        // x += m @ Wp2 + bp2 ; x += LoRA_p2(m)
        gemm(false, mb, Wp2 + (long long)i * C4 * CC, x, bp2 + i * CC,
             BT, CC, C4, C4, CC, CC, 0, 0, 0, 0, 0, 0, 1, 1, 1.0f, 1);
        lora(mb, BT, C4, Ap2 + (long long)i * C4 * RR, Bp2 + (long long)i * RR * CC, x, CC, 0, CC, lo);
    }

    // final LN, slice token rows, LM head
    ln_kernel<<<BT, 256>>>(x, lnfg, lnfb, h);
    copy_xt_kernel<<<(BB * TTOK * CC) / 256, 256>>>(h, xt);
    // logits = xt @ wte^T
    gemm(true, xt, wte, out, nullptr,
         BB * TTOK, VV, CC, CC, CC, VV, 0, 0, 0, 0, 0, 0, 1, 1, 1.0f, 0);
    // logits += SCALE * xt @ Alm @ Blm
    lora(xt, BB * TTOK, CC, Alm, Blm, out, VV, 0, VV, lo);
    // att_map (layer 11) into output tail
    copy_att_kernel<<<(ATT_ELEMS / 4) / 256, 256>>>(out + LOGITS_ELEMS);
}

// round 13
// speedup vs baseline: 1.9708x; 1.9708x over previous
#include <cuda_runtime.h>
#include <math.h>
#include <stdint.h>

// ---------------- problem constants ----------------
#define BB     4
#define TTOK   512
#define LIMG   256
#define TT     768
#define CC     768
#define HH     12
#define DH     64
#define NLAYER 12
#define VV     50257
#define RR     4
#define LSCALE 8.0f
#define C3     2304
#define C4     3072
#define BT     (BB*TT)
#define ATT_ELEMS   (BB*HH*TT*TT)
#define LOGITS_ELEMS ((long long)BB*TTOK*VV)

// ---------------- scratch (device globals; no allocs allowed) ----------------
__device__ float g_x  [BB*TT*CC];
__device__ float g_h  [BB*TT*CC];
__device__ float g_qkv[BB*TT*C3];
__device__ float g_att[ATT_ELEMS];
__device__ float g_y  [BB*TT*CC];
__device__ float g_m  [BB*TT*C4];
__device__ float g_lo [BT*RR];
__device__ float g_xt [BB*TTOK*CC];
__device__ int   g_tok_is64;
// transposed weights ([N,K] K-major rows for the MMA B operand)
__device__ float g_WqkvT[NLAYER*C3*CC];
__device__ float g_WoT  [NLAYER*CC*CC];
__device__ float g_WfcT [NLAYER*C4*CC];
__device__ float g_Wp2T [NLAYER*CC*C4];
__device__ float g_vt   [BB*HH*DH*TT];

// ---------------- helpers ----------------
__device__ __forceinline__ float rtf(float x){
    float y; asm("cvt.rna.tf32.f32 %0, %1;" : "=f"(y) : "f"(x)); return y;
}
__device__ __forceinline__ void mma8(float* c, const uint32_t* a, const uint32_t* b){
    asm volatile("mma.sync.aligned.m16n8k8.row.col.f32.tf32.tf32.f32 "
        "{%0,%1,%2,%3}, {%4,%5,%6,%7}, {%8,%9}, {%0,%1,%2,%3};"
        : "+f"(c[0]), "+f"(c[1]), "+f"(c[2]), "+f"(c[3])
        : "r"(a[0]), "r"(a[1]), "r"(a[2]), "r"(a[3]), "r"(b[0]), "r"(b[1]));
}

// ---------------- tf32 mma.sync GEMM: C[M,N] = alpha*A[M,K]@B[N,K]^T (+bias)(+C)(+LoRA)
// A: [M,K] row-major (lda); B: [N,K] row-major (ldb) — both K-major.
// M % 128 == 0, K % 32 == 0. N arbitrary (guarded). flags bit0 = accumulate.
// Optional fused LoRA up-projection: if loT != null, adds
//   LSCALE * (loT[row,0:4] . loB[0:4, col])  with loB row stride = N.
// Operands rounded to tf32 (cvt.rna) once, at the SMEM store.
#define PADK 36
#define STG_F (2*128*PADK)          // floats per stage (A+B)
#define GSMEM (2*STG_F*4)           // 73728 bytes
__global__ void __launch_bounds__(256) gemm_tf32(
    const float* __restrict__ A, const float* __restrict__ B, float* __restrict__ C,
    const float* __restrict__ bias,
    const float* __restrict__ loT, const float* __restrict__ loB,
    int M, int N, int K, int lda, int ldb, int ldc,
    long long sAb, long long sAh, long long sBb, long long sBh,
    long long sCb, long long sCh, int Hdiv, float alpha, int flags)
{
    extern __shared__ float smem[];
    const int tid = threadIdx.x;
    const int wid = tid >> 5, lane = tid & 31;
    const int wm = wid & 3, wn = wid >> 2;          // 4 x 2 warp grid
    const int g = lane >> 2, t = lane & 3;

    { int z = blockIdx.z; int zb = z / Hdiv, zh = z - zb * Hdiv;
      A += zb * sAb + (long long)zh * sAh;
      B += zb * sBb + (long long)zh * sBh;
      C += zb * sCb + (long long)zh * sCh; }

    const int m0 = blockIdx.y * 128, n0 = blockIdx.x * 128;

    // global load mapping: 4 float4 per tile per thread
    int lrow[4], lc4[4]; bool bok[4];
    #pragma unroll
    for (int i = 0; i < 4; i++) {
        int lin = tid + i * 256;          // 0..1023
        lrow[i] = lin >> 3;               // 0..127
        lc4[i]  = (lin & 7) * 4;          // 0,4,..28
        bok[i]  = (n0 + lrow[i]) < N;
    }

    float acc[2][8][4];
    #pragma unroll
    for (int mi = 0; mi < 2; mi++)
        #pragma unroll
        for (int ni = 0; ni < 8; ni++)
            #pragma unroll
            for (int j = 0; j < 4; j++) acc[mi][ni][j] = 0.f;

    const int nch = K >> 5;
    float4 pa[4], pb[4];
    int cur = 0;

    // prologue: chunk 0 -> smem stage 0
    #pragma unroll
    for (int i = 0; i < 4; i++) {
        pa[i] = *(const float4*)(A + (size_t)(m0 + lrow[i]) * lda + lc4[i]);
        pb[i] = bok[i] ? *(const float4*)(B + (size_t)(n0 + lrow[i]) * ldb + lc4[i])
                       : make_float4(0.f,0.f,0.f,0.f);
    }
    {
        float* As = smem; float* Bs = smem + 128 * PADK;
        #pragma unroll
        for (int i = 0; i < 4; i++) {
            float* pA = As + lrow[i] * PADK + lc4[i];
            pA[0]=rtf(pa[i].x); pA[1]=rtf(pa[i].y); pA[2]=rtf(pa[i].z); pA[3]=rtf(pa[i].w);
            float* pB = Bs + lrow[i] * PADK + lc4[i];
            pB[0]=rtf(pb[i].x); pB[1]=rtf(pb[i].y); pB[2]=rtf(pb[i].z); pB[3]=rtf(pb[i].w);
        }
    }
    __syncthreads();

    for (int c = 0; c < nch; c++) {
        if (c + 1 < nch) {
            int kt = (c + 1) << 5;
            #pragma unroll
            for (int i = 0; i < 4; i++) {
                pa[i] = *(const float4*)(A + (size_t)(m0 + lrow[i]) * lda + kt + lc4[i]);
                pb[i] = bok[i] ? *(const float4*)(B + (size_t)(n0 + lrow[i]) * ldb + kt + lc4[i])
                               : make_float4(0.f,0.f,0.f,0.f);
            }
        }
        // compute on stage cur
        {
            const float* As = smem + cur * STG_F;
            const float* Bs = As + 128 * PADK;
            const int mr = wm * 32 + g;
            const int nr = wn * 64 + g;
            #pragma unroll
            for (int k8 = 0; k8 < 32; k8 += 8) {
                uint32_t af[2][4];
                #pragma unroll
                for (int mi = 0; mi < 2; mi++) {
                    int r = mr + mi * 16;
                    af[mi][0] = __float_as_uint(As[(r    ) * PADK + k8 + t    ]);
                    af[mi][1] = __float_as_uint(As[(r + 8) * PADK + k8 + t    ]);
                    af[mi][2] = __float_as_uint(As[(r    ) * PADK + k8 + t + 4]);
                    af[mi][3] = __float_as_uint(As[(r + 8) * PADK + k8 + t + 4]);
                }
                uint32_t bf[8][2];
                #pragma unroll
                for (int ni = 0; ni < 8; ni++) {
                    int n = nr + ni * 8;
                    bf[ni][0] = __float_as_uint(Bs[n * PADK + k8 + t    ]);
                    bf[ni][1] = __float_as_uint(Bs[n * PADK + k8 + t + 4]);
                }
                #pragma unroll
                for (int mi = 0; mi < 2; mi++)
                    #pragma unroll
                    for (int ni = 0; ni < 8; ni++)
                        mma8(acc[mi][ni], af[mi], bf[ni]);
            }
        }
        if (c + 1 < nch) {
            __syncthreads();
            float* As = smem + (cur ^ 1) * STG_F;
            float* Bs = As + 128 * PADK;
            #pragma unroll
            for (int i = 0; i < 4; i++) {
                float* pA = As + lrow[i] * PADK + lc4[i];
                pA[0]=rtf(pa[i].x); pA[1]=rtf(pa[i].y); pA[2]=rtf(pa[i].z); pA[3]=rtf(pa[i].w);
                float* pB = Bs + lrow[i] * PADK + lc4[i];
                pB[0]=rtf(pb[i].x); pB[1]=rtf(pb[i].y); pB[2]=rtf(pb[i].z); pB[3]=rtf(pb[i].w);
            }
            __syncthreads();
            cur ^= 1;
        }
    }

    // epilogue (optionally fused rank-4 LoRA up-projection)
    const int doacc = flags & 1;
    #pragma unroll
    for (int mi = 0; mi < 2; mi++) {
        #pragma unroll
        for (int half = 0; half < 2; half++) {
            int row = m0 + wm * 32 + mi * 16 + g + half * 8;
            float* Cr = C + (size_t)row * ldc;
            float4 tv = make_float4(0.f,0.f,0.f,0.f);
            if (loT) tv = *(const float4*)(loT + (size_t)row * 4);
            #pragma unroll
            for (int ni = 0; ni < 8; ni++) {
                int col = n0 + wn * 64 + ni * 8 + 2 * t;
                #pragma unroll
                for (int e = 0; e < 2; e++) {
                    int cn = col + e;
                    if (cn < N) {
                        float w = acc[mi][ni][half * 2 + e] * alpha;
                        if (bias) w += bias[cn];
                        if (loT)
                            w += LSCALE * (tv.x * loB[cn] + tv.y * loB[(size_t)N + cn]
                                         + tv.z * loB[2 * (size_t)N + cn] + tv.w * loB[3 * (size_t)N + cn]);
                        if (doacc) w += Cr[cn];
                        Cr[cn] = w;
                    }
                }
            }
        }
    }
}

// ---------------- block reductions ----------------
__device__ __forceinline__ float bsum(float v) {
    __shared__ float sh[32];
    #pragma unroll
    for (int o = 16; o; o >>= 1) v += __shfl_xor_sync(0xffffffffu, v, o);
    if ((threadIdx.x & 31) == 0) sh[threadIdx.x >> 5] = v;
    __syncthreads();
    if (threadIdx.x == 0) { float s = 0.f; int nw = blockDim.x >> 5;
        for (int i = 0; i < nw; i++) s += sh[i]; sh[0] = s; }
    __syncthreads();
    float r = sh[0]; __syncthreads(); return r;
}
__device__ __forceinline__ float bmax(float v) {
    __shared__ float sh[32];
    #pragma unroll
    for (int o = 16; o; o >>= 1) v = fmaxf(v, __shfl_xor_sync(0xffffffffu, v, o));
    if ((threadIdx.x & 31) == 0) sh[threadIdx.x >> 5] = v;
    __syncthreads();
    if (threadIdx.x == 0) { float s = -3.0e38f; int nw = blockDim.x >> 5;
        for (int i = 0; i < nw; i++) s = fmaxf(s, sh[i]); sh[0] = s; }
    __syncthreads();
    float r = sh[0]; __syncthreads(); return r;
}

// ---------------- misc kernels ----------------
__global__ void detect_kernel(const int* __restrict__ tok32) {
    __shared__ int bad;
    if (threadIdx.x == 0) bad = 0;
    __syncthreads();
    for (int i = threadIdx.x; i < 1024; i += blockDim.x)
        if (tok32[2 * i + 1] != 0) bad = 1;
    __syncthreads();
    if (threadIdx.x == 0) g_tok_is64 = (bad == 0) ? 1 : 0;
}

__global__ void embed_kernel(const int* __restrict__ tok32, const float* __restrict__ img,
                             const float* __restrict__ wte, const float* __restrict__ wpe,
                             float* __restrict__ x) {
    int idx = blockIdx.x * blockDim.x + threadIdx.x;
    int b = idx / (TT * CC);
    int r = idx - b * (TT * CC);
    int t = r / CC, c = r - t * CC;
    float v;
    if (t < LIMG) v = img[((long long)b * LIMG + t) * CC + c];
    else {
        int tt = t - LIMG, tix = b * TTOK + tt;
        int tok = g_tok_is64 ? tok32[2 * tix] : tok32[tix];
        v = wte[(long long)tok * CC + c] + wpe[(long long)tt * CC + c];
    }
    x[idx] = v;
}

__global__ void ln_kernel(const float* __restrict__ in, const float* __restrict__ g,
                          const float* __restrict__ b, float* __restrict__ out) {
    long long row = blockIdx.x;
    const float* xr = in + row * CC;
    float* orow = out + row * CC;
    float s = 0.f;
    for (int c = threadIdx.x; c < CC; c += blockDim.x) s += xr[c];
    float mean = bsum(s) * (1.0f / CC);
    float s2 = 0.f;
    for (int c = threadIdx.x; c < CC; c += blockDim.x) { float d = xr[c] - mean; s2 += d * d; }
    float var = bsum(s2) * (1.0f / CC);
    float inv = rsqrtf(var + 1e-5f);
    for (int c = threadIdx.x; c < CC; c += blockDim.x)
        orow[c] = (xr[c] - mean) * inv * g[c] + b[c];
}

__global__ void softmax_kernel(float* __restrict__ att) {
    long long row = blockIdx.x;
    int t = (int)(row % TT);
    int len = t + 1;
    float* p = att + row * TT;
    float mx = -3.0e38f;
    for (int j = threadIdx.x; j < len; j += blockDim.x) mx = fmaxf(mx, p[j]);
    mx = bmax(mx);
    float s = 0.f;
    for (int j = threadIdx.x; j < len; j += blockDim.x) { float e = __expf(p[j] - mx); p[j] = e; s += e; }
    s = bsum(s);
    float inv = 1.0f / s;
    for (int j = threadIdx.x; j < TT; j += blockDim.x)
        p[j] = (j < len) ? p[j] * inv : 0.0f;
}

__global__ void gelu_kernel(float* __restrict__ p, int n) {
    int i = blockIdx.x * blockDim.x + threadIdx.x;
    if (i < n) {
        float x = p[i];
        float u = 0.7978845608028654f * (x + 0.044715f * x * x * x);
        p[i] = 0.5f * x * (1.0f + tanhf(u));
    }
}

// weight transpose [K,N] -> [N,K]. block (32,8)
__global__ void transpose_w(const float* __restrict__ in, float* __restrict__ out,
                            int K, int N, long long sIn, long long sOut) {
    __shared__ float t[32][33];
    long long z = blockIdx.z;
    in += z * sIn; out += z * sOut;
    int n0 = blockIdx.x * 32, k0 = blockIdx.y * 32;
    int tx = threadIdx.x, ty = threadIdx.y;
    #pragma unroll
    for (int i = 0; i < 32; i += 8) t[ty + i][tx] = in[(size_t)(k0 + ty + i) * N + n0 + tx];
    __syncthreads();
    #pragma unroll
    for (int i = 0; i < 32; i += 8) out[(size_t)(n0 + ty + i) * K + k0 + tx] = t[tx][ty + i];
}

// v transpose: g_vt[b,h,d,t] = qkv[b,t,2C + h*64 + d]. block (32,8)
__global__ void transpose_v(const float* __restrict__ qkv, float* __restrict__ vt) {
    __shared__ float t[32][33];
    int z = blockIdx.z;           // b*HH + h
    int b = z / HH, h = z - b * HH;
    int t0 = blockIdx.x * 32, d0 = blockIdx.y * 32;
    int tx = threadIdx.x, ty = threadIdx.y;
    const float* src = qkv + (size_t)b * TT * C3 + 2 * CC + h * DH;
    #pragma unroll
    for (int i = 0; i < 32; i += 8) t[ty + i][tx] = src[(size_t)(t0 + ty + i) * C3 + d0 + tx];
    __syncthreads();
    float* dst = vt + (size_t)z * DH * TT;
    #pragma unroll
    for (int i = 0; i < 32; i += 8) dst[(size_t)(d0 + ty + i) * TT + t0 + tx] = t[tx][ty + i];
}

// LoRA down: tmp[M,4] = X[M,K] @ A[K,4]
__global__ void lora_down_kernel(const float* __restrict__ X, int K,
                                 const float* __restrict__ Ad, float* __restrict__ outT) {
    int m = blockIdx.x;
    const float* xr = X + (long long)m * K;
    float a0 = 0, a1 = 0, a2 = 0, a3 = 0;
    for (int k = threadIdx.x; k < K; k += blockDim.x) {
        float xv = xr[k];
        float4 av = *reinterpret_cast<const float4*>(Ad + (long long)k * 4);
        a0 += xv * av.x; a1 += xv * av.y; a2 += xv * av.z; a3 += xv * av.w;
    }
    __shared__ float sh[128 * 4];
    int tid = threadIdx.x;
    sh[tid*4+0] = a0; sh[tid*4+1] = a1; sh[tid*4+2] = a2; sh[tid*4+3] = a3;
    __syncthreads();
    for (int s = 64; s > 0; s >>= 1) {
        if (tid < s) {
            sh[tid*4+0] += sh[(tid+s)*4+0]; sh[tid*4+1] += sh[(tid+s)*4+1];
            sh[tid*4+2] += sh[(tid+s)*4+2]; sh[tid*4+3] += sh[(tid+s)*4+3];
        }
        __syncthreads();
    }
    if (tid == 0) { outT[m*4+0]=sh[0]; outT[m*4+1]=sh[1]; outT[m*4+2]=sh[2]; outT[m*4+3]=sh[3]; }
}
__global__ void lora_up_kernel(const float* __restrict__ T4, const float* __restrict__ Bu,
                               float* __restrict__ out, long long ldc, int N) {
    int n = blockIdx.x * blockDim.x + threadIdx.x;
    int m = blockIdx.y;
    if (n >= N) return;
    float4 t = *reinterpret_cast<const float4*>(T4 + m * 4);
    float v = t.x * Bu[n] + t.y * Bu[(long long)N + n] + t.z * Bu[2LL*N + n] + t.w * Bu[3LL*N + n];
    out[(long long)m * ldc + n] += LSCALE * v;
}

__global__ void copy_xt_kernel(const float* __restrict__ hbuf, float* __restrict__ xt) {
    int idx = blockIdx.x * blockDim.x + threadIdx.x;
    int m = idx / CC, c = idx - m * CC;
    int b = m / TTOK, t = LIMG + (m - b * TTOK);
    xt[idx] = hbuf[((long long)b * TT + t) * CC + c];
}
__global__ void copy_att_kernel(float* __restrict__ dst) {
    int i = blockIdx.x * blockDim.x + threadIdx.x;
    reinterpret_cast<float4*>(dst)[i] = reinterpret_cast<const float4*>(g_att)[i];
}

// ---------------- host helpers ----------------
static void gemmT(const float* A, const float* B, float* C, const float* bias,
                  const float* loT, const float* loB,
                  int M, int N, int K, int lda, int ldb, int ldc,
                  long long sAb, long long sAh, long long sBb, long long sBh,
                  long long sCb, long long sCh, int Hdiv, int Z, float alpha, int flags) {
    dim3 gr((N + 127) / 128, M / 128, Z);
    gemm_tf32<<<gr, 256, GSMEM>>>(A, B, C, bias, loT, loB, M, N, K, lda, ldb, ldc,
                                  sAb, sAh, sBb, sBh, sCb, sCh, Hdiv, alpha, flags);
}
static void lora(const float* X, int M, int K, const float* Ad, const float* Bu,
                 float* out, long long ldc, int colofs, int N, float* lobuf) {
    lora_down_kernel<<<M, 128>>>(X, K, Ad, lobuf);
    dim3 gr((N + 255) / 256, M);
    lora_up_kernel<<<gr, 256>>>(lobuf, Bu, out + colofs, ldc, N);
}

extern "C" void kernel_launch(void* const* d_in, const int* in_sizes, int n_in,
                              void* d_out, int out_size) {
    (void)in_sizes; (void)n_in; (void)out_size;
    const int*   tok  = (const int*)  d_in[0];
    const float* img  = (const float*)d_in[1];
    const float* wte  = (const float*)d_in[2];
    const float* wpe  = (const float*)d_in[3];
    const float* ln1g = (const float*)d_in[4];
    const float* ln1b = (const float*)d_in[5];
    const float* Wqkv = (const float*)d_in[6];
    const float* bqkv = (const float*)d_in[7];
    const float* Aq   = (const float*)d_in[8];
    const float* Bq   = (const float*)d_in[9];
    const float* Av   = (const float*)d_in[10];
    const float* Bv   = (const float*)d_in[11];
    const float* Wo   = (const float*)d_in[12];
    const float* bo   = (const float*)d_in[13];
    const float* Ao   = (const float*)d_in[14];
    const float* Bo   = (const float*)d_in[15];
    const float* ln2g = (const float*)d_in[16];
    const float* ln2b = (const float*)d_in[17];
    const float* Wfc  = (const float*)d_in[18];
    const float* bfc  = (const float*)d_in[19];
    const float* Afc  = (const float*)d_in[20];
    const float* Bfc  = (const float*)d_in[21];
    const float* Wp2  = (const float*)d_in[22];
    const float* bp2  = (const float*)d_in[23];
    const float* Ap2  = (const float*)d_in[24];
    const float* Bp2  = (const float*)d_in[25];
    const float* lnfg = (const float*)d_in[26];
    const float* lnfb = (const float*)d_in[27];
    const float* Alm  = (const float*)d_in[28];
    const float* Blm  = (const float*)d_in[29];
    float* out = (float*)d_out;

    cudaFuncSetAttribute(gemm_tf32, cudaFuncAttributeMaxDynamicSharedMemorySize, GSMEM);

    float *x,*h,*qkv,*att,*y,*mb,*lo,*xt,*WqkvT,*WoT,*WfcT,*Wp2T,*vt;
    cudaGetSymbolAddress((void**)&x, g_x);       cudaGetSymbolAddress((void**)&h, g_h);
    cudaGetSymbolAddress((void**)&qkv, g_qkv);   cudaGetSymbolAddress((void**)&att, g_att);
    cudaGetSymbolAddress((void**)&y, g_y);       cudaGetSymbolAddress((void**)&mb, g_m);
    cudaGetSymbolAddress((void**)&lo, g_lo);     cudaGetSymbolAddress((void**)&xt, g_xt);
    cudaGetSymbolAddress((void**)&WqkvT, g_WqkvT); cudaGetSymbolAddress((void**)&WoT, g_WoT);
    cudaGetSymbolAddress((void**)&WfcT, g_WfcT);   cudaGetSymbolAddress((void**)&Wp2T, g_Wp2T);
    cudaGetSymbolAddress((void**)&vt, g_vt);

    detect_kernel<<<1, 256>>>(tok);
    embed_kernel<<<(BB*TT*CC)/256, 256>>>(tok, img, wte, wpe, x);

    // weight prep: transpose to [N,K]
    {
        dim3 bl(32, 8);
        transpose_w<<<dim3(C3/32, CC/32, NLAYER), bl>>>(Wqkv, WqkvT, CC, C3, (long long)CC*C3, (long long)C3*CC);
        transpose_w<<<dim3(CC/32, CC/32, NLAYER), bl>>>(Wo,   WoT,   CC, CC, (long long)CC*CC, (long long)CC*CC);
        transpose_w<<<dim3(C4/32, CC/32, NLAYER), bl>>>(Wfc,  WfcT,  CC, C4, (long long)CC*C4, (long long)C4*CC);
        transpose_w<<<dim3(CC/32, C4/32, NLAYER), bl>>>(Wp2,  Wp2T,  C4, CC, (long long)C4*CC, (long long)CC*C4);
    }

    const float ascale = 1.0f / 8.0f;
    for (int i = 0; i < NLAYER; i++) {
        ln_kernel<<<BT, 256>>>(x, ln1g + i*CC, ln1b + i*CC, h);
        // qkv = h @ Wqkv + bqkv ; LoRA q/v into column subranges (separate)
        gemmT(h, WqkvT + (long long)i*C3*CC, qkv, bqkv + i*C3, nullptr, nullptr,
              BT, C3, CC, CC, CC, C3, 0,0,0,0,0,0, 1, 1, 1.0f, 0);
        lora(h, BT, CC, Aq + (long long)i*CC*RR, Bq + (long long)i*RR*CC, qkv, C3, 0,    CC, lo);
        lora(h, BT, CC, Av + (long long)i*CC*RR, Bv + (long long)i*RR*CC, qkv, C3, 2*CC, CC, lo);
        transpose_v<<<dim3(TT/32, DH/32, BB*HH), dim3(32,8)>>>(qkv, vt);
        // scores = (1/8) q @ k^T
        gemmT(qkv, qkv + CC, att, nullptr, nullptr, nullptr,
              TT, TT, DH, C3, C3, TT,
              (long long)TT*C3, DH, (long long)TT*C3, DH,
              (long long)HH*TT*TT, (long long)TT*TT, HH, BB*HH, ascale, 0);
        softmax_kernel<<<BB*HH*TT, 256>>>(att);
        // y = att @ v   (B = v^T [64, T])
        gemmT(att, vt, y, nullptr, nullptr, nullptr,
              TT, DH, TT, TT, TT, CC,
              (long long)HH*TT*TT, (long long)TT*TT,
              (long long)HH*DH*TT, (long long)DH*TT,
              (long long)TT*CC, DH, HH, BB*HH, 1.0f, 0);
        // x += y @ Wo + bo + LoRA_o(y)   (LoRA fused into epilogue)
        lora_down_kernel<<<BT, 128>>>(y, CC, Ao + (long long)i*CC*RR, lo);
        gemmT(y, WoT + (long long)i*CC*CC, x, bo + i*CC, lo, Bo + (long long)i*RR*CC,
              BT, CC, CC, CC, CC, CC, 0,0,0,0,0,0, 1, 1, 1.0f, 1);
        ln_kernel<<<BT, 256>>>(x, ln2g + i*CC, ln2b + i*CC, h);
        // m = h @ Wfc + bfc + LoRA_fc(h) (fused) ; gelu
        lora_down_kernel<<<BT, 128>>>(h, CC, Afc + (long long)i*CC*RR, lo);
        gemmT(h, WfcT + (long long)i*C4*CC, mb, bfc + i*C4, lo, Bfc + (long long)i*RR*C4,
              BT, C4, CC, CC, CC, C4, 0,0,0,0,0,0, 1, 1, 1.0f, 0);
        gelu_kernel<<<(BT*C4)/256, 256>>>(mb, BT*C4);
        // x += m @ Wp2 + bp2 + LoRA_p2(m) (fused)
        lora_down_kernel<<<BT, 128>>>(mb, C4, Ap2 + (long long)i*C4*RR, lo);
        gemmT(mb, Wp2T + (long long)i*CC*C4, x, bp2 + i*CC, lo, Bp2 + (long long)i*RR*CC,
              BT, CC, C4, C4, C4, CC, 0,0,0,0,0,0, 1, 1, 1.0f, 1);
    }

    ln_kernel<<<BT, 256>>>(x, lnfg, lnfb, h);
    copy_xt_kernel<<<(BB*TTOK*CC)/256, 256>>>(h, xt);
    // logits = xt @ wte^T + LoRA_lm(xt) (fused; wte already [V,C] K-major)
    lora_down_kernel<<<BB*TTOK, 128>>>(xt, CC, Alm, lo);
    gemmT(xt, wte, out, nullptr, lo, Blm,
          BB*TTOK, VV, CC, CC, CC, VV, 0,0,0,0,0,0, 1, 1, 1.0f, 0);
    copy_att_kernel<<<(ATT_ELEMS/4)/256, 256>>>(out + LOGITS_ELEMS);
}

// round 14
// speedup vs baseline: 2.7053x; 1.3727x over previous
#include <cuda_runtime.h>
#include <math.h>
#include <stdint.h>

// ---------------- problem constants ----------------
#define BB     4
#define TTOK   512
#define LIMG   256
#define TT     768
#define CC     768
#define HH     12
#define DH     64
#define NLAYER 12
#define VV     50257
#define RR     4
#define LSCALE 8.0f
#define C3     2304
#define C4     3072
#define BT     (BB*TT)
#define ATT_ELEMS   (BB*HH*TT*TT)
#define LOGITS_ELEMS ((long long)BB*TTOK*VV)

// ---------------- scratch (device globals; no allocs allowed) ----------------
__device__ float g_x  [BB*TT*CC];
__device__ float g_h  [BB*TT*CC];
__device__ float g_qkv[BB*TT*C3];
__device__ float g_att[ATT_ELEMS];
__device__ float g_y  [BB*TT*CC];
__device__ float g_m  [BB*TT*C4];
__device__ float g_lo [BT*RR];
__device__ float g_xt [BB*TTOK*CC];
__device__ int   g_tok_is64;
// transposed / rounded weights ([N,K] K-major rows, tf32-rounded)
__device__ float g_WqkvT[NLAYER*C3*CC];
__device__ float g_WoT  [NLAYER*CC*CC];
__device__ float g_WfcT [NLAYER*C4*CC];
__device__ float g_Wp2T [NLAYER*CC*C4];
__device__ float g_wteR [VV*CC];
__device__ float g_vt   [BB*HH*DH*TT];

// ---------------- helpers ----------------
__device__ __forceinline__ float rtf(float x){
    float y; asm("cvt.rna.tf32.f32 %0, %1;" : "=f"(y) : "f"(x)); return y;
}
__device__ __forceinline__ uint32_t smem_u32(const void* p){
    uint32_t a;
    asm("{ .reg .u64 t; cvta.to.shared.u64 t, %1; cvt.u32.u64 %0, t; }" : "=r"(a) : "l"(p));
    return a;
}
__device__ __forceinline__ void mma8(float* c, const uint32_t* a, const uint32_t* b){
    asm volatile("mma.sync.aligned.m16n8k8.row.col.f32.tf32.tf32.f32 "
        "{%0,%1,%2,%3}, {%4,%5,%6,%7}, {%8,%9}, {%0,%1,%2,%3};"
        : "+f"(c[0]), "+f"(c[1]), "+f"(c[2]), "+f"(c[3])
        : "r"(a[0]), "r"(a[1]), "r"(a[2]), "r"(a[3]), "r"(b[0]), "r"(b[1]));
}
#define CPA(dst, src, sz) asm volatile("cp.async.cg.shared.global [%0], [%1], 16, %2;" \
    :: "r"(dst), "l"(src), "r"(sz) : "memory")
#define CP_COMMIT() asm volatile("cp.async.commit_group;" ::: "memory")
#define CP_WAIT2()  asm volatile("cp.async.wait_group 2;" ::: "memory")

// ---------------- tf32 mma.sync GEMM (cp.async 3-stage pipeline) --------------
// C[M,N] = alpha*A[M,K]@B[N,K]^T (+bias)(+C)(+LoRA). A,B PRE-ROUNDED to tf32.
// flags: bit0 accumulate, bit1 round output to tf32, bit2 causal skip (n0>m0+127).
#define PADK 36
#define STG_B 36864                  // bytes per stage (A 18432 + B 18432)
#define STG_F 9216                   // floats per stage
#define GSMEM (3*STG_B)              // 110592 bytes
__global__ void __launch_bounds__(256) gemm_tf32(
    const float* __restrict__ A, const float* __restrict__ B, float* __restrict__ C,
    const float* __restrict__ bias,
    const float* __restrict__ loT, const float* __restrict__ loB,
    int M, int N, int K, int lda, int ldb, int ldc,
    long long sAb, long long sAh, long long sBb, long long sBh,
    long long sCb, long long sCh, int Hdiv, float alpha, int flags)
{
    extern __shared__ float smem[];
    const int tid = threadIdx.x;
    const int wid = tid >> 5, lane = tid & 31;
    const int wm = wid & 3, wn = wid >> 2;          // 4 x 2 warp grid
    const int g = lane >> 2, t = lane & 3;

    { int z = blockIdx.z; int zb = z / Hdiv, zh = z - zb * Hdiv;
      A += zb * sAb + (long long)zh * sAh;
      B += zb * sBb + (long long)zh * sBh;
      C += zb * sCb + (long long)zh * sCh; }

    const int m0 = blockIdx.y * 128, n0 = blockIdx.x * 128;
    if ((flags & 4) && n0 > m0 + 127) return;   // causal: block fully masked

    const uint32_t sbase = smem_u32(smem);

    // global <-> smem mapping: 4 x 16B per operand per thread per chunk
    const float* pA[4]; const float* pB[4]; uint32_t dA[4]; uint32_t szB[4];
    #pragma unroll
    for (int i = 0; i < 4; i++) {
        int lin = tid + i * 256;
        int lrow = lin >> 3;
        int lc4  = (lin & 7) * 4;
        pA[i] = A + (size_t)(m0 + lrow) * lda + lc4;
        bool bok = (n0 + lrow) < N;
        pB[i] = bok ? (B + (size_t)(n0 + lrow) * ldb + lc4) : B;
        szB[i] = bok ? 16u : 0u;
        dA[i] = (uint32_t)(lrow * (PADK * 4) + lc4 * 4);
    }

    float acc[2][8][4];
    #pragma unroll
    for (int mi = 0; mi < 2; mi++)
        #pragma unroll
        for (int ni = 0; ni < 8; ni++)
            #pragma unroll
            for (int j = 0; j < 4; j++) acc[mi][ni][j] = 0.f;

    const int nch = K >> 5;

    #define ISSUE(cc) do{ int _s = (cc) % 3; uint32_t _sb = sbase + _s * STG_B; \
        int _kt = (cc) << 5; \
        _Pragma("unroll") for (int i = 0; i < 4; i++) { \
            CPA(_sb + dA[i], pA[i] + _kt, 16u); \
            CPA(_sb + 18432u + dA[i], pB[i] + (szB[i] ? _kt : 0), szB[i]); } }while(0)

    // prologue: chunks 0..2 (pad with empty groups so wait_group 2 is exact)
    #pragma unroll
    for (int p = 0; p < 3; p++) {
        if (p < nch) ISSUE(p);
        CP_COMMIT();
    }

    for (int c = 0; c < nch; c++) {
        CP_WAIT2();
        __syncthreads();
        {
            const float* As = smem + (c % 3) * STG_F;
            const float* Bs = As + 128 * PADK;
            const int mr = wm * 32 + g;
            const int nr = wn * 64 + g;
            #pragma unroll
            for (int k8 = 0; k8 < 32; k8 += 8) {
                uint32_t af[2][4];
                #pragma unroll
                for (int mi = 0; mi < 2; mi++) {
                    int r = mr + mi * 16;
                    af[mi][0] = __float_as_uint(As[(r    ) * PADK + k8 + t    ]);
                    af[mi][1] = __float_as_uint(As[(r + 8) * PADK + k8 + t    ]);
                    af[mi][2] = __float_as_uint(As[(r    ) * PADK + k8 + t + 4]);
                    af[mi][3] = __float_as_uint(As[(r + 8) * PADK + k8 + t + 4]);
                }
                uint32_t bf[8][2];
                #pragma unroll
                for (int ni = 0; ni < 8; ni++) {
                    int n = nr + ni * 8;
                    bf[ni][0] = __float_as_uint(Bs[n * PADK + k8 + t    ]);
                    bf[ni][1] = __float_as_uint(Bs[n * PADK + k8 + t + 4]);
                }
                #pragma unroll
                for (int mi = 0; mi < 2; mi++)
                    #pragma unroll
                    for (int ni = 0; ni < 8; ni++)
                        mma8(acc[mi][ni], af[mi], bf[ni]);
            }
        }
        __syncthreads();
        if (c + 3 < nch) ISSUE(c + 3);
        CP_COMMIT();
    }
    #undef ISSUE

    // epilogue (bias + optional LoRA + optional accumulate + optional tf32 round)
    const int doacc = flags & 1, dornd = flags & 2;
    #pragma unroll
    for (int mi = 0; mi < 2; mi++) {
        #pragma unroll
        for (int half = 0; half < 2; half++) {
            int row = m0 + wm * 32 + mi * 16 + g + half * 8;
            float* Cr = C + (size_t)row * ldc;
            float4 tv = make_float4(0.f,0.f,0.f,0.f);
            if (loT) tv = *(const float4*)(loT + (size_t)row * 4);
            #pragma unroll
            for (int ni = 0; ni < 8; ni++) {
                int col = n0 + wn * 64 + ni * 8 + 2 * t;
                #pragma unroll
                for (int e = 0; e < 2; e++) {
                    int cn = col + e;
                    if (cn < N) {
                        float w = acc[mi][ni][half * 2 + e] * alpha;
                        if (bias) w += bias[cn];
                        if (loT)
                            w += LSCALE * (tv.x * loB[cn] + tv.y * loB[(size_t)N + cn]
                                         + tv.z * loB[2 * (size_t)N + cn] + tv.w * loB[3 * (size_t)N + cn]);
                        if (doacc) w += Cr[cn];
                        if (dornd) w = rtf(w);
                        Cr[cn] = w;
                    }
                }
            }
        }
    }
}

// ---------------- block reductions ----------------
__device__ __forceinline__ float bsum(float v) {
    __shared__ float sh[32];
    #pragma unroll
    for (int o = 16; o; o >>= 1) v += __shfl_xor_sync(0xffffffffu, v, o);
    if ((threadIdx.x & 31) == 0) sh[threadIdx.x >> 5] = v;
    __syncthreads();
    if (threadIdx.x == 0) { float s = 0.f; int nw = blockDim.x >> 5;
        for (int i = 0; i < nw; i++) s += sh[i]; sh[0] = s; }
    __syncthreads();
    float r = sh[0]; __syncthreads(); return r;
}
__device__ __forceinline__ float bmax(float v) {
    __shared__ float sh[32];
    #pragma unroll
    for (int o = 16; o; o >>= 1) v = fmaxf(v, __shfl_xor_sync(0xffffffffu, v, o));
    if ((threadIdx.x & 31) == 0) sh[threadIdx.x >> 5] = v;
    __syncthreads();
    if (threadIdx.x == 0) { float s = -3.0e38f; int nw = blockDim.x >> 5;
        for (int i = 0; i < nw; i++) s = fmaxf(s, sh[i]); sh[0] = s; }
    __syncthreads();
    float r = sh[0]; __syncthreads(); return r;
}

// ---------------- misc kernels ----------------
__global__ void detect_kernel(const int* __restrict__ tok32) {
    __shared__ int bad;
    if (threadIdx.x == 0) bad = 0;
    __syncthreads();
    for (int i = threadIdx.x; i < 1024; i += blockDim.x)
        if (tok32[2 * i + 1] != 0) bad = 1;
    __syncthreads();
    if (threadIdx.x == 0) g_tok_is64 = (bad == 0) ? 1 : 0;
}

__global__ void embed_kernel(const int* __restrict__ tok32, const float* __restrict__ img,
                             const float* __restrict__ wte, const float* __restrict__ wpe,
                             float* __restrict__ x) {
    int idx = blockIdx.x * blockDim.x + threadIdx.x;
    int b = idx / (TT * CC);
    int r = idx - b * (TT * CC);
    int t = r / CC, c = r - t * CC;
    float v;
    if (t < LIMG) v = img[((long long)b * LIMG + t) * CC + c];
    else {
        int tt = t - LIMG, tix = b * TTOK + tt;
        int tok = g_tok_is64 ? tok32[2 * tix] : tok32[tix];
        v = wte[(long long)tok * CC + c] + wpe[(long long)tt * CC + c];
    }
    x[idx] = v;
}

// layernorm; output rounded to tf32 (it is an MMA operand)
__global__ void ln_kernel(const float* __restrict__ in, const float* __restrict__ g,
                          const float* __restrict__ b, float* __restrict__ out) {
    long long row = blockIdx.x;
    const float* xr = in + row * CC;
    float* orow = out + row * CC;
    float s = 0.f;
    for (int c = threadIdx.x; c < CC; c += blockDim.x) s += xr[c];
    float mean = bsum(s) * (1.0f / CC);
    float s2 = 0.f;
    for (int c = threadIdx.x; c < CC; c += blockDim.x) { float d = xr[c] - mean; s2 += d * d; }
    float var = bsum(s2) * (1.0f / CC);
    float inv = rsqrtf(var + 1e-5f);
    for (int c = threadIdx.x; c < CC; c += blockDim.x)
        orow[c] = rtf((xr[c] - mean) * inv * g[c] + b[c]);
}

// causal softmax; probs rounded to tf32 (MMA operand; zeros beyond t)
__global__ void softmax_kernel(float* __restrict__ att) {
    long long row = blockIdx.x;
    int t = (int)(row % TT);
    int len = t + 1;
    float* p = att + row * TT;
    float mx = -3.0e38f;
    for (int j = threadIdx.x; j < len; j += blockDim.x) mx = fmaxf(mx, p[j]);
    mx = bmax(mx);
    float s = 0.f;
    for (int j = threadIdx.x; j < len; j += blockDim.x) { float e = __expf(p[j] - mx); p[j] = e; s += e; }
    s = bsum(s);
    float inv = 1.0f / s;
    for (int j = threadIdx.x; j < TT; j += blockDim.x)
        p[j] = (j < len) ? rtf(p[j] * inv) : 0.0f;
}

__global__ void gelu_kernel(float* __restrict__ p, int n) {
    int i = blockIdx.x * blockDim.x + threadIdx.x;
    if (i < n) {
        float x = p[i];
        float u = 0.7978845608028654f * (x + 0.044715f * x * x * x);
        p[i] = rtf(0.5f * x * (1.0f + tanhf(u)));
    }
}

__global__ void roundcp_kernel(const float* __restrict__ in, float* __restrict__ out, int n) {
    int i = blockIdx.x * blockDim.x + threadIdx.x;
    if (i < n) out[i] = rtf(in[i]);
}

// weight transpose [K,N] -> [N,K], rounded. block (32,8)
__global__ void transpose_w(const float* __restrict__ in, float* __restrict__ out,
                            int K, int N, long long sIn, long long sOut) {
    __shared__ float t[32][33];
    long long z = blockIdx.z;
    in += z * sIn; out += z * sOut;
    int n0 = blockIdx.x * 32, k0 = blockIdx.y * 32;
    int tx = threadIdx.x, ty = threadIdx.y;
    #pragma unroll
    for (int i = 0; i < 32; i += 8) t[ty + i][tx] = in[(size_t)(k0 + ty + i) * N + n0 + tx];
    __syncthreads();
    #pragma unroll
    for (int i = 0; i < 32; i += 8) out[(size_t)(n0 + ty + i) * K + k0 + tx] = rtf(t[tx][ty + i]);
}

// v transpose: g_vt[b,h,d,t] = qkv[...] (qkv already rounded). block (32,8)
__global__ void transpose_v(const float* __restrict__ qkv, float* __restrict__ vt) {
    __shared__ float t[32][33];
    int z = blockIdx.z;
    int b = z / HH, h = z - b * HH;
    int t0 = blockIdx.x * 32, d0 = blockIdx.y * 32;
    int tx = threadIdx.x, ty = threadIdx.y;
    const float* src = qkv + (size_t)b * TT * C3 + 2 * CC + h * DH;
    #pragma unroll
    for (int i = 0; i < 32; i += 8) t[ty + i][tx] = src[(size_t)(t0 + ty + i) * C3 + d0 + tx];
    __syncthreads();
    float* dst = vt + (size_t)z * DH * TT;
    #pragma unroll
    for (int i = 0; i < 32; i += 8) dst[(size_t)(d0 + ty + i) * TT + t0 + tx] = t[tx][ty + i];
}

// LoRA down: tmp[M,4] = X[M,K] @ A[K,4]
__global__ void lora_down_kernel(const float* __restrict__ X, int K,
                                 const float* __restrict__ Ad, float* __restrict__ outT) {
    int m = blockIdx.x;
    const float* xr = X + (long long)m * K;
    float a0 = 0, a1 = 0, a2 = 0, a3 = 0;
    for (int k = threadIdx.x; k < K; k += blockDim.x) {
        float xv = xr[k];
        float4 av = *reinterpret_cast<const float4*>(Ad + (long long)k * 4);
        a0 += xv * av.x; a1 += xv * av.y; a2 += xv * av.z; a3 += xv * av.w;
    }
    __shared__ float sh[128 * 4];
    int tid = threadIdx.x;
    sh[tid*4+0] = a0; sh[tid*4+1] = a1; sh[tid*4+2] = a2; sh[tid*4+3] = a3;
    __syncthreads();
    for (int s = 64; s > 0; s >>= 1) {
        if (tid < s) {
            sh[tid*4+0] += sh[(tid+s)*4+0]; sh[tid*4+1] += sh[(tid+s)*4+1];
            sh[tid*4+2] += sh[(tid+s)*4+2]; sh[tid*4+3] += sh[(tid+s)*4+3];
        }
        __syncthreads();
    }
    if (tid == 0) { outT[m*4+0]=sh[0]; outT[m*4+1]=sh[1]; outT[m*4+2]=sh[2]; outT[m*4+3]=sh[3]; }
}
// LoRA up into qkv column subranges; rounds final value (MMA operand)
__global__ void lora_up_kernel(const float* __restrict__ T4, const float* __restrict__ Bu,
                               float* __restrict__ out, long long ldc, int N) {
    int n = blockIdx.x * blockDim.x + threadIdx.x;
    int m = blockIdx.y;
    if (n >= N) return;
    float4 t = *reinterpret_cast<const float4*>(T4 + m * 4);
    float v = t.x * Bu[n] + t.y * Bu[(long long)N + n] + t.z * Bu[2LL*N + n] + t.w * Bu[3LL*N + n];
    long long off = (long long)m * ldc + n;
    out[off] = rtf(out[off] + LSCALE * v);
}

__global__ void copy_xt_kernel(const float* __restrict__ hbuf, float* __restrict__ xt) {
    int idx = blockIdx.x * blockDim.x + threadIdx.x;
    int m = idx / CC, c = idx - m * CC;
    int b = m / TTOK, t = LIMG + (m - b * TTOK);
    xt[idx] = hbuf[((long long)b * TT + t) * CC + c];   // hbuf (ln out) already rounded
}
__global__ void copy_att_kernel(float* __restrict__ dst) {
    int i = blockIdx.x * blockDim.x + threadIdx.x;
    reinterpret_cast<float4*>(dst)[i] = reinterpret_cast<const float4*>(g_att)[i];
}

// ---------------- host helpers ----------------
static void gemmT(const float* A, const float* B, float* C, const float* bias,
                  const float* loT, const float* loB,
                  int M, int N, int K, int lda, int ldb, int ldc,
                  long long sAb, long long sAh, long long sBb, long long sBh,
                  long long sCb, long long sCh, int Hdiv, int Z, float alpha, int flags) {
    dim3 gr((N + 127) / 128, M / 128, Z);
    gemm_tf32<<<gr, 256, GSMEM>>>(A, B, C, bias, loT, loB, M, N, K, lda, ldb, ldc,
                                  sAb, sAh, sBb, sBh, sCb, sCh, Hdiv, alpha, flags);
}
static void lora(const float* X, int M, int K, const float* Ad, const float* Bu,
                 float* out, long long ldc, int colofs, int N, float* lobuf) {
    lora_down_kernel<<<M, 128>>>(X, K, Ad, lobuf);
    dim3 gr((N + 255) / 256, M);
    lora_up_kernel<<<gr, 256>>>(lobuf, Bu, out + colofs, ldc, N);
}

extern "C" void kernel_launch(void* const* d_in, const int* in_sizes, int n_in,
                              void* d_out, int out_size) {
    (void)in_sizes; (void)n_in; (void)out_size;
    const int*   tok  = (const int*)  d_in[0];
    const float* img  = (const float*)d_in[1];
    const float* wte  = (const float*)d_in[2];
    const float* wpe  = (const float*)d_in[3];
    const float* ln1g = (const float*)d_in[4];
    const float* ln1b = (const float*)d_in[5];
    const float* Wqkv = (const float*)d_in[6];
    const float* bqkv = (const float*)d_in[7];
    const float* Aq   = (const float*)d_in[8];
    const float* Bq   = (const float*)d_in[9];
    const float* Av   = (const float*)d_in[10];
    const float* Bv   = (const float*)d_in[11];
    const float* Wo   = (const float*)d_in[12];
    const float* bo   = (const float*)d_in[13];
    const float* Ao   = (const float*)d_in[14];
    const float* Bo   = (const float*)d_in[15];
    const float* ln2g = (const float*)d_in[16];
    const float* ln2b = (const float*)d_in[17];
    const float* Wfc  = (const float*)d_in[18];
    const float* bfc  = (const float*)d_in[19];
    const float* Afc  = (const float*)d_in[20];
    const float* Bfc  = (const float*)d_in[21];
    const float* Wp2  = (const float*)d_in[22];
    const float* bp2  = (const float*)d_in[23];
    const float* Ap2  = (const float*)d_in[24];
    const float* Bp2  = (const float*)d_in[25];
    const float* lnfg = (const float*)d_in[26];
    const float* lnfb = (const float*)d_in[27];
    const float* Alm  = (const float*)d_in[28];
    const float* Blm  = (const float*)d_in[29];
    float* out = (float*)d_out;

    cudaFuncSetAttribute(gemm_tf32, cudaFuncAttributeMaxDynamicSharedMemorySize, GSMEM);

    float *x,*h,*qkv,*att,*y,*mb,*lo,*xt,*WqkvT,*WoT,*WfcT,*Wp2T,*wteR,*vt;
    cudaGetSymbolAddress((void**)&x, g_x);       cudaGetSymbolAddress((void**)&h, g_h);
    cudaGetSymbolAddress((void**)&qkv, g_qkv);   cudaGetSymbolAddress((void**)&att, g_att);
    cudaGetSymbolAddress((void**)&y, g_y);       cudaGetSymbolAddress((void**)&mb, g_m);
    cudaGetSymbolAddress((void**)&lo, g_lo);     cudaGetSymbolAddress((void**)&xt, g_xt);
    cudaGetSymbolAddress((void**)&WqkvT, g_WqkvT); cudaGetSymbolAddress((void**)&WoT, g_WoT);
    cudaGetSymbolAddress((void**)&WfcT, g_WfcT);   cudaGetSymbolAddress((void**)&Wp2T, g_Wp2T);
    cudaGetSymbolAddress((void**)&wteR, g_wteR);   cudaGetSymbolAddress((void**)&vt, g_vt);

    detect_kernel<<<1, 256>>>(tok);
    embed_kernel<<<(BB*TT*CC)/256, 256>>>(tok, img, wte, wpe, x);

    // weight prep: transpose + round to tf32; wte rounded copy for LM head
    {
        dim3 bl(32, 8);
        transpose_w<<<dim3(C3/32, CC/32, NLAYER), bl>>>(Wqkv, WqkvT, CC, C3, (long long)CC*C3, (long long)C3*CC);
        transpose_w<<<dim3(CC/32, CC/32, NLAYER), bl>>>(Wo,   WoT,   CC, CC, (long long)CC*CC, (long long)CC*CC);
        transpose_w<<<dim3(C4/32, CC/32, NLAYER), bl>>>(Wfc,  WfcT,  CC, C4, (long long)CC*C4, (long long)C4*CC);
        transpose_w<<<dim3(CC/32, C4/32, NLAYER), bl>>>(Wp2,  Wp2T,  C4, CC, (long long)C4*CC, (long long)CC*C4);
        roundcp_kernel<<<(VV*CC + 255)/256, 256>>>(wte, wteR, VV*CC);
    }

    const float ascale = 1.0f / 8.0f;
    for (int i = 0; i < NLAYER; i++) {
        ln_kernel<<<BT, 256>>>(x, ln1g + i*CC, ln1b + i*CC, h);
        // qkv = h @ Wqkv + bqkv (output rounded -> MMA operand); LoRA q/v then re-round
        gemmT(h, WqkvT + (long long)i*C3*CC, qkv, bqkv + i*C3, nullptr, nullptr,
              BT, C3, CC, CC, CC, C3, 0,0,0,0,0,0, 1, 1, 1.0f, 2);
        lora(h, BT, CC, Aq + (long long)i*CC*RR, Bq + (long long)i*RR*CC, qkv, C3, 0,    CC, lo);
        lora(h, BT, CC, Av + (long long)i*CC*RR, Bv + (long long)i*RR*CC, qkv, C3, 2*CC, CC, lo);
        transpose_v<<<dim3(TT/32, DH/32, BB*HH), dim3(32,8)>>>(qkv, vt);
        // scores = (1/8) q @ k^T   (causal block skip)
        gemmT(qkv, qkv + CC, att, nullptr, nullptr, nullptr,
              TT, TT, DH, C3, C3, TT,
              (long long)TT*C3, DH, (long long)TT*C3, DH,
              (long long)HH*TT*TT, (long long)TT*TT, HH, BB*HH, ascale, 4);
        softmax_kernel<<<BB*HH*TT, 256>>>(att);
        // y = att @ v  (output rounded -> operand of Wo GEMM / LoRA)
        gemmT(att, vt, y, nullptr, nullptr, nullptr,
              TT, DH, TT, TT, TT, CC,
              (long long)HH*TT*TT, (long long)TT*TT,
              (long long)HH*DH*TT, (long long)DH*TT,
              (long long)TT*CC, DH, HH, BB*HH, 1.0f, 2);
        // x += y @ Wo + bo + LoRA_o(y)
        lora_down_kernel<<<BT, 128>>>(y, CC, Ao + (long long)i*CC*RR, lo);
        gemmT(y, WoT + (long long)i*CC*CC, x, bo + i*CC, lo, Bo + (long long)i*RR*CC,
              BT, CC, CC, CC, CC, CC, 0,0,0,0,0,0, 1, 1, 1.0f, 1);
        ln_kernel<<<BT, 256>>>(x, ln2g + i*CC, ln2b + i*CC, h);
        // m = h @ Wfc + bfc + LoRA_fc(h); gelu rounds
        lora_down_kernel<<<BT, 128>>>(h, CC, Afc + (long long)i*CC*RR, lo);
        gemmT(h, WfcT + (long long)i*C4*CC, mb, bfc + i*C4, lo, Bfc + (long long)i*RR*C4,
              BT, C4, CC, CC, CC, C4, 0,0,0,0,0,0, 1, 1, 1.0f, 0);
        gelu_kernel<<<(BT*C4)/256, 256>>>(mb, BT*C4);
        // x += m @ Wp2 + bp2 + LoRA_p2(m)
        lora_down_kernel<<<BT, 128>>>(mb, C4, Ap2 + (long long)i*C4*RR, lo);
        gemmT(mb, Wp2T + (long long)i*CC*C4, x, bp2 + i*CC, lo, Bp2 + (long long)i*RR*CC,
              BT, CC, C4, C4, C4, CC, 0,0,0,0,0,0, 1, 1, 1.0f, 1);
    }

    ln_kernel<<<BT, 256>>>(x, lnfg, lnfb, h);
    copy_xt_kernel<<<(BB*TTOK*CC)/256, 256>>>(h, xt);
    // logits = xt @ wteR^T + LoRA_lm(xt)
    lora_down_kernel<<<BB*TTOK, 128>>>(xt, CC, Alm, lo);
    gemmT(xt, wteR, out, nullptr, lo, Blm,
          BB*TTOK, VV, CC, CC, CC, VV, 0,0,0,0,0,0, 1, 1, 1.0f, 0);
    copy_att_kernel<<<(ATT_ELEMS/4)/256, 256>>>(out + LOGITS_ELEMS);
}